// round 7
// baseline (speedup 1.0000x reference)
#include <cuda_runtime.h>
#include <cuda_bf16.h>
#include <cstdint>

// Shapes (fixed)
#define T_DIM   1024
#define N_BATCH 8
#define E_DIM   1024
#define H_HEADS 16
#define D_HEAD  64
#define B_HEADS 128
#define M_ROWS  8192
#define QKV_LD  3072
#define ROW_STRIDE 24576   // 8*3072

typedef __nv_bfloat16 bf16;

// ---------------- scratch (allocation-free) ----------------
__device__ bf16  g_qh [(size_t)M_ROWS * E_DIM];
__device__ bf16  g_ql [(size_t)M_ROWS * E_DIM];
__device__ bf16  g_wih[(size_t)QKV_LD * E_DIM];
__device__ bf16  g_wil[(size_t)QKV_LD * E_DIM];
__device__ bf16  g_woh[(size_t)E_DIM * E_DIM];
__device__ bf16  g_wol[(size_t)E_DIM * E_DIM];
__device__ float g_qkv [(size_t)M_ROWS * QKV_LD];
__device__ bf16  g_qkvh[(size_t)M_ROWS * QKV_LD];
__device__ bf16  g_qkvl[(size_t)M_ROWS * QKV_LD];
__device__ bf16  g_vth[(size_t)N_BATCH * E_DIM * T_DIM];   // [n][d][s]
__device__ bf16  g_vtl[(size_t)N_BATCH * E_DIM * T_DIM];
__device__ float g_attn[(size_t)B_HEADS * T_DIM * T_DIM];  // pass1: e-values
__device__ bf16  g_ph  [(size_t)B_HEADS * T_DIM * T_DIM];
__device__ bf16  g_pl  [(size_t)B_HEADS * T_DIM * T_DIM];
__device__ float g_ctx [(size_t)M_ROWS * E_DIM];
__device__ bf16  g_ch [(size_t)M_ROWS * E_DIM];
__device__ bf16  g_cl [(size_t)M_ROWS * E_DIM];

#define DEVFN __device__ __forceinline__

DEVFN uint32_t smem_u32(const void* p) {
    uint32_t a;
    asm("{ .reg .u64 t; cvta.to.shared.u64 t, %1; cvt.u32.u64 %0, t; }" : "=r"(a) : "l"(p));
    return a;
}
DEVFN void cpa16(uint32_t s, const void* g) {
    asm volatile("cp.async.cg.shared.global [%0], [%1], 16;" :: "r"(s), "l"(g));
}
DEVFN void cp_commit() { asm volatile("cp.async.commit_group;" ::: "memory"); }
template<int N> DEVFN void cp_wait() { asm volatile("cp.async.wait_group %0;" :: "n"(N) : "memory"); }
DEVFN void ldsm4(uint32_t* r, uint32_t a) {
    asm volatile("ldmatrix.sync.aligned.m8n8.x4.shared.b16 {%0,%1,%2,%3}, [%4];"
                 : "=r"(r[0]), "=r"(r[1]), "=r"(r[2]), "=r"(r[3]) : "r"(a));
}
DEVFN void mma16816(float* c, const uint32_t* a, const uint32_t* b) {
    asm volatile(
        "mma.sync.aligned.m16n8k16.row.col.f32.bf16.bf16.f32 "
        "{%0,%1,%2,%3}, {%4,%5,%6,%7}, {%8,%9}, {%0,%1,%2,%3};"
        : "+f"(c[0]), "+f"(c[1]), "+f"(c[2]), "+f"(c[3])
        : "r"(a[0]), "r"(a[1]), "r"(a[2]), "r"(a[3]), "r"(b[0]), "r"(b[1]));
}
DEVFN float rsum4(float v) {
    v += __shfl_xor_sync(0xffffffffu, v, 1);
    v += __shfl_xor_sync(0xffffffffu, v, 2);
    return v;
}
DEVFN float rmax4(float v) {
    v = fmaxf(v, __shfl_xor_sync(0xffffffffu, v, 1));
    v = fmaxf(v, __shfl_xor_sync(0xffffffffu, v, 2));
    return v;
}

// ---------------------------------------------------------------------------
// Split-bf16 NT GEMM core (ldmatrix + mma.sync): C = alpha*A·B^T (+bias)
// CTA tile 128 x BN, BK=32, 8 warps of WM x WN. Pitch 80B (conflict-free ldsm).
// ---------------------------------------------------------------------------
template<int BN, int WM, int WN, bool HAS_BIAS>
DEVFN void gemm_core(const bf16* __restrict__ Ah, const bf16* __restrict__ Al, int lda,
                     const bf16* __restrict__ Bh, const bf16* __restrict__ Bl, int ldb,
                     const float* __restrict__ bias, float alpha,
                     float* __restrict__ C, int ldc, int K, int m0, int n0, char* smem)
{
    constexpr int PITCH = 80;
    constexpr int ASZ = 128 * PITCH;
    constexpr int BSZ = BN  * PITCH;
    constexpr int STAGE = 2 * ASZ + 2 * BSZ;
    const int tid = threadIdx.x;
    const uint32_t sbase = smem_u32(smem);

    auto load_stage = [&](int st, int kk) {
        uint32_t s0 = sbase + st * STAGE;
#pragma unroll
        for (int i = 0; i < 2; ++i) {
            int id = tid + i * 256;
            int row = id >> 2, ck = id & 3;
            uint32_t so = s0 + row * PITCH + ck * 16;
            size_t go = (size_t)(m0 + row) * lda + kk + ck * 8;
            cpa16(so, Ah + go);
            cpa16(so + ASZ, Al + go);
        }
#pragma unroll
        for (int i = 0; i < (BN * 4) / 256; ++i) {
            int id = tid + i * 256;
            int row = id >> 2, ck = id & 3;
            uint32_t so = s0 + 2 * ASZ + row * PITCH + ck * 16;
            size_t go = (size_t)(n0 + row) * ldb + kk + ck * 8;
            cpa16(so, Bh + go);
            cpa16(so + BSZ, Bl + go);
        }
    };

    constexpr int WGM = 128 / WM;
    constexpr int MT = WM / 16, NT = WN / 8;
    const int lane = tid & 31, wid = tid >> 5;
    const int wm = wid % WGM, wn = wid / WGM;
    const int lg = lane >> 3, lr = lane & 7;
    const int r0 = lane >> 2, c0 = (lane & 3) * 2;
    // ldmatrix lane offsets (A: tiles m0-7/k0, m8-15/k0, m0-7/k8, m8-15/k8;
    //                        B: tiles n0-7/k0, n0-7/k8, n8-15/k0, n8-15/k8)
    const uint32_t aLOff = (uint32_t)((wm * WM + (lg & 1) * 8 + lr) * PITCH + (lg >> 1) * 16);
    const uint32_t bLOff = (uint32_t)((wn * WN + (lg >> 1) * 8 + lr) * PITCH + (lg & 1) * 16);

    float acc[MT][NT][4];
#pragma unroll
    for (int i = 0; i < MT; i++)
#pragma unroll
        for (int j = 0; j < NT; j++) {
            acc[i][j][0] = 0.f; acc[i][j][1] = 0.f; acc[i][j][2] = 0.f; acc[i][j][3] = 0.f;
        }

    const int NC = K >> 5;
    load_stage(0, 0);
    cp_commit();

    for (int c = 0; c < NC; ++c) {
        if (c + 1 < NC) { load_stage((c + 1) & 1, (c + 1) * 32); cp_commit(); cp_wait<1>(); }
        else            { cp_wait<0>(); }
        __syncthreads();

        const uint32_t sA = sbase + (c & 1) * STAGE;
        const uint32_t sB = sA + 2 * ASZ;
#pragma unroll
        for (int ks = 0; ks < 2; ++ks) {
            uint32_t ah[MT][4], al[MT][4], bh[NT / 2][4], bl[NT / 2][4];
#pragma unroll
            for (int mt = 0; mt < MT; ++mt) {
                ldsm4(ah[mt], sA + aLOff + mt * 16 * PITCH + ks * 32);
                ldsm4(al[mt], sA + ASZ + aLOff + mt * 16 * PITCH + ks * 32);
            }
#pragma unroll
            for (int np = 0; np < NT / 2; ++np) {
                ldsm4(bh[np], sB + bLOff + np * 16 * PITCH + ks * 32);
                ldsm4(bl[np], sB + BSZ + bLOff + np * 16 * PITCH + ks * 32);
            }
#pragma unroll
            for (int mt = 0; mt < MT; ++mt)
#pragma unroll
                for (int nt = 0; nt < NT; ++nt) {
                    mma16816(acc[mt][nt], ah[mt], &bh[nt >> 1][(nt & 1) * 2]);
                    mma16816(acc[mt][nt], ah[mt], &bl[nt >> 1][(nt & 1) * 2]);
                    mma16816(acc[mt][nt], al[mt], &bh[nt >> 1][(nt & 1) * 2]);
                }
        }
        __syncthreads();
    }

#pragma unroll
    for (int mt = 0; mt < MT; ++mt) {
#pragma unroll
        for (int nt = 0; nt < NT; ++nt) {
            int row = m0 + wm * WM + mt * 16 + r0;
            int col = n0 + wn * WN + nt * 8 + c0;
            float bx = HAS_BIAS ? bias[col] : 0.f;
            float by = HAS_BIAS ? bias[col + 1] : 0.f;
            float2 v0 = make_float2(alpha * acc[mt][nt][0] + bx, alpha * acc[mt][nt][1] + by);
            float2 v1 = make_float2(alpha * acc[mt][nt][2] + bx, alpha * acc[mt][nt][3] + by);
            *reinterpret_cast<float2*>(C + (size_t)row * ldc + col) = v0;
            *reinterpret_cast<float2*>(C + (size_t)(row + 8) * ldc + col) = v1;
        }
    }
}

#define SMEM_128 (2 * (2 * 128 * 80 + 2 * 128 * 80))   // 81920
#define SMEM_64  (2 * (2 * 128 * 80 + 2 * 64 * 80))    // 61440

__global__ __launch_bounds__(256) void k_qkv(const float* __restrict__ bias) {
    extern __shared__ char smem[];
    gemm_core<128, 64, 32, true>(g_qh, g_ql, E_DIM, g_wih, g_wil, E_DIM,
                                 bias, 1.f, g_qkv, QKV_LD, E_DIM,
                                 blockIdx.y * 128, blockIdx.x * 128, smem);
}

__global__ __launch_bounds__(256) void k_pv() {
    extern __shared__ char smem[];
    const int hb = blockIdx.y, n = hb >> 4, h = hb & 15;
    const bf16* Ah = g_ph + ((size_t)hb << 20);
    const bf16* Al = g_pl + ((size_t)hb << 20);
    const bf16* Bh = g_vth + ((size_t)n * E_DIM + h * D_HEAD) * T_DIM;
    const bf16* Bl = g_vtl + ((size_t)n * E_DIM + h * D_HEAD) * T_DIM;
    float* C = g_ctx + (size_t)n * E_DIM + h * D_HEAD;
    gemm_core<64, 32, 32, false>(Ah, Al, T_DIM, Bh, Bl, T_DIM,
                                 nullptr, 1.f, C, N_BATCH * E_DIM, T_DIM,
                                 blockIdx.x * 128, 0, smem);
}

__global__ __launch_bounds__(256) void k_out(const float* __restrict__ bias, float* __restrict__ out) {
    extern __shared__ char smem[];
    gemm_core<128, 64, 32, true>(g_ch, g_cl, E_DIM, g_woh, g_wol, E_DIM,
                                 bias, 1.f, out, E_DIM, E_DIM,
                                 blockIdx.y * 128, blockIdx.x * 128, smem);
}

// ---------------------------------------------------------------------------
// Fused scores + softmax: CTA = (t-tile 128, head). Streams 8 K-tiles.
// Pass1: scores via MMA, online row max/sum, write e=exp(x-m_tile) fp32.
// Pass2: p = e * exp(m_tile - m_final)/sum -> (p_hi, p_lo).
// ---------------------------------------------------------------------------
#define P2 144                          // pitch for 64-elem bf16 rows (128B + 16 pad)
#define QSZ (128 * P2)                  // 18432
#define SC_SMEM (2 * QSZ + 2 * 2 * QSZ) // Qh,Ql + 2 stages x (Kh,Kl) = 110592

__global__ __launch_bounds__(256) void k_scores_sm() {
    extern __shared__ char smem[];
    __shared__ float s_m[128], s_s[128], s_scale[128];
    __shared__ float s_pmax[4][128], s_psum[4][128], s_f[8][128];

    const int tid = threadIdx.x, lane = tid & 31, wid = tid >> 5;
    const int wm = wid & 1, wn = wid >> 1;          // WM=64, WN=32
    const int lg = lane >> 3, lr = lane & 7;
    const uint32_t sbase = smem_u32(smem);
    const int hb = blockIdx.y, n = hb >> 4, h = hb & 15;
    const int t0 = blockIdx.x * 128;

    const size_t qoff = ((size_t)t0 * 8 + n) * QKV_LD + h * 64;
    const size_t koffb = (size_t)n * QKV_LD + E_DIM + h * 64;

    auto load64 = [&](uint32_t dst, const bf16* gp) {
#pragma unroll
        for (int i = 0; i < 4; ++i) {
            int id = tid + i * 256;
            int row = id >> 3, ck = id & 7;
            cpa16(dst + row * P2 + ck * 16, gp + (size_t)row * ROW_STRIDE + ck * 8);
        }
    };

    if (tid < 128) { s_m[tid] = -1e30f; s_s[tid] = 0.f; }

    // prologue: Q (hi+lo) + K tile 0
    load64(sbase,        g_qkvh + qoff);
    load64(sbase + QSZ,  g_qkvl + qoff);
    load64(sbase + 2 * QSZ,        g_qkvh + koffb);
    load64(sbase + 2 * QSZ + QSZ,  g_qkvl + koffb);
    cp_commit();

    const uint32_t aLOff = (uint32_t)((wm * 64 + (lg & 1) * 8 + lr) * P2 + (lg >> 1) * 16);
    const uint32_t bLOff = (uint32_t)((wn * 32 + (lg >> 1) * 8 + lr) * P2 + (lg & 1) * 16);
    const int lrow0 = wm * 64 + (lane >> 2);        // + mt*16 ; +8 for upper half
    const int c0 = (lane & 3) * 2;

    for (int st = 0; st < 8; ++st) {
        if (st + 1 < 8) {
            uint32_t dst = sbase + 2 * QSZ + ((st + 1) & 1) * 2 * QSZ;
            const size_t ko = koffb + (size_t)(st + 1) * 128 * ROW_STRIDE;
            load64(dst,       g_qkvh + ko);
            load64(dst + QSZ, g_qkvl + ko);
            cp_commit();
            cp_wait<1>();
        } else {
            cp_wait<0>();
        }
        __syncthreads();

        float acc[4][4][4];
#pragma unroll
        for (int i = 0; i < 4; i++)
#pragma unroll
            for (int j = 0; j < 4; j++) {
                acc[i][j][0] = 0.f; acc[i][j][1] = 0.f; acc[i][j][2] = 0.f; acc[i][j][3] = 0.f;
            }
        const uint32_t sK = sbase + 2 * QSZ + (st & 1) * 2 * QSZ;
#pragma unroll
        for (int ks = 0; ks < 4; ++ks) {
            uint32_t ah[4][4], al[4][4], bh[2][4], bl[2][4];
#pragma unroll
            for (int mt = 0; mt < 4; ++mt) {
                ldsm4(ah[mt], sbase + aLOff + mt * 16 * P2 + ks * 32);
                ldsm4(al[mt], sbase + QSZ + aLOff + mt * 16 * P2 + ks * 32);
            }
#pragma unroll
            for (int np = 0; np < 2; ++np) {
                ldsm4(bh[np], sK + bLOff + np * 16 * P2 + ks * 32);
                ldsm4(bl[np], sK + QSZ + bLOff + np * 16 * P2 + ks * 32);
            }
#pragma unroll
            for (int mt = 0; mt < 4; ++mt)
#pragma unroll
                for (int nt = 0; nt < 4; ++nt) {
                    mma16816(acc[mt][nt], ah[mt], &bh[nt >> 1][(nt & 1) * 2]);
                    mma16816(acc[mt][nt], ah[mt], &bl[nt >> 1][(nt & 1) * 2]);
                    mma16816(acc[mt][nt], al[mt], &bh[nt >> 1][(nt & 1) * 2]);
                }
        }

        // --- row max (scaled) ---
#pragma unroll
        for (int mt = 0; mt < 4; ++mt) {
            float m0 = -1e30f, m1 = -1e30f;
#pragma unroll
            for (int nt = 0; nt < 4; ++nt) {
                m0 = fmaxf(m0, fmaxf(acc[mt][nt][0], acc[mt][nt][1]));
                m1 = fmaxf(m1, fmaxf(acc[mt][nt][2], acc[mt][nt][3]));
            }
            m0 = rmax4(m0 * 0.125f);
            m1 = rmax4(m1 * 0.125f);
            if ((lane & 3) == 0) {
                s_pmax[wn][lrow0 + mt * 16]     = m0;
                s_pmax[wn][lrow0 + mt * 16 + 8] = m1;
            }
        }
        __syncthreads();
        if (tid < 128) {
            float tm = fmaxf(fmaxf(s_pmax[0][tid], s_pmax[1][tid]),
                             fmaxf(s_pmax[2][tid], s_pmax[3][tid]));
            float mo = s_m[tid];
            float mn = fmaxf(mo, tm);
            s_scale[tid] = __expf(mo - mn);
            s_m[tid] = mn;
            s_f[st][tid] = mn;     // remember tile-time max
        }
        __syncthreads();

        // --- e = exp(x - m_new), write, row-sum ---
        float* ebase = g_attn + ((size_t)hb << 20) + (size_t)t0 * 1024;
#pragma unroll
        for (int mt = 0; mt < 4; ++mt) {
            const int r0l = lrow0 + mt * 16;
            const float mv0 = s_m[r0l], mv1 = s_m[r0l + 8];
            float sum0 = 0.f, sum1 = 0.f;
#pragma unroll
            for (int nt = 0; nt < 4; ++nt) {
                const int col = st * 128 + wn * 32 + nt * 8 + c0;
                float e0 = __expf(acc[mt][nt][0] * 0.125f - mv0);
                float e1 = __expf(acc[mt][nt][1] * 0.125f - mv0);
                float e2 = __expf(acc[mt][nt][2] * 0.125f - mv1);
                float e3 = __expf(acc[mt][nt][3] * 0.125f - mv1);
                *reinterpret_cast<float2*>(ebase + (size_t)r0l * 1024 + col)       = make_float2(e0, e1);
                *reinterpret_cast<float2*>(ebase + (size_t)(r0l + 8) * 1024 + col) = make_float2(e2, e3);
                sum0 += e0 + e1;
                sum1 += e2 + e3;
            }
            sum0 = rsum4(sum0);
            sum1 = rsum4(sum1);
            if ((lane & 3) == 0) {
                s_psum[wn][r0l]     = sum0;
                s_psum[wn][r0l + 8] = sum1;
            }
        }
        __syncthreads();
        if (tid < 128) {
            float ts = s_psum[0][tid] + s_psum[1][tid] + s_psum[2][tid] + s_psum[3][tid];
            s_s[tid] = s_s[tid] * s_scale[tid] + ts;
        }
        __syncthreads();
    }

    // finalize per-tile factors: f = exp(m_tile - m_final) / sum
    if (tid < 128) {
        float inv = 1.0f / s_s[tid];
        float mf = s_m[tid];
#pragma unroll
        for (int st = 0; st < 8; ++st)
            s_f[st][tid] = __expf(s_f[st][tid] - mf) * inv;
    }
    __syncthreads();

    // pass 2: p = e * f -> (hi, lo)
    const float* ebase = g_attn + ((size_t)hb << 20) + (size_t)t0 * 1024;
    bf16* phb = g_ph + ((size_t)hb << 20) + (size_t)t0 * 1024;
    bf16* plb = g_pl + ((size_t)hb << 20) + (size_t)t0 * 1024;
#pragma unroll 4
    for (int i = 0; i < 128; ++i) {
        int flat = i * 256 + tid;
        int row = flat >> 8, cc = flat & 255;
        float4 e = *reinterpret_cast<const float4*>(ebase + (size_t)row * 1024 + cc * 4);
        float f = s_f[cc >> 5][row];
        float p0 = e.x * f, p1 = e.y * f, p2 = e.z * f, p3 = e.w * f;
        bf16 h0 = __float2bfloat16(p0), h1 = __float2bfloat16(p1);
        bf16 h2 = __float2bfloat16(p2), h3 = __float2bfloat16(p3);
        bf16 l0 = __float2bfloat16(p0 - __bfloat162float(h0));
        bf16 l1 = __float2bfloat16(p1 - __bfloat162float(h1));
        bf16 l2 = __float2bfloat16(p2 - __bfloat162float(h2));
        bf16 l3 = __float2bfloat16(p3 - __bfloat162float(h3));
        union { __nv_bfloat162 b[2]; uint2 u; } H, L;
        H.b[0] = __halves2bfloat162(h0, h1); H.b[1] = __halves2bfloat162(h2, h3);
        L.b[0] = __halves2bfloat162(l0, l1); L.b[1] = __halves2bfloat162(l2, l3);
        *reinterpret_cast<uint2*>(phb + (size_t)row * 1024 + cc * 4) = H.u;
        *reinterpret_cast<uint2*>(plb + (size_t)row * 1024 + cc * 4) = L.u;
    }
}

// ---------------- split fp32 -> (hi, lo) bf16 ----------------
__global__ __launch_bounds__(256) void split_kernel(
    const float* __restrict__ x, bf16* __restrict__ h, bf16* __restrict__ l) {
    size_t i = (size_t)blockIdx.x * 256 + threadIdx.x;
    float4 v = reinterpret_cast<const float4*>(x)[i];
    bf16 h0 = __float2bfloat16(v.x), h1 = __float2bfloat16(v.y);
    bf16 h2 = __float2bfloat16(v.z), h3 = __float2bfloat16(v.w);
    bf16 l0 = __float2bfloat16(v.x - __bfloat162float(h0));
    bf16 l1 = __float2bfloat16(v.y - __bfloat162float(h1));
    bf16 l2 = __float2bfloat16(v.z - __bfloat162float(h2));
    bf16 l3 = __float2bfloat16(v.w - __bfloat162float(h3));
    union { __nv_bfloat162 b[2]; uint2 u; } H, L;
    H.b[0] = __halves2bfloat162(h0, h1); H.b[1] = __halves2bfloat162(h2, h3);
    L.b[0] = __halves2bfloat162(l0, l1); L.b[1] = __halves2bfloat162(l2, l3);
    *reinterpret_cast<uint2*>(h + i * 4) = H.u;
    *reinterpret_cast<uint2*>(l + i * 4) = L.u;
}

// ---------------- V transpose ----------------
__global__ __launch_bounds__(256) void vt_kernel() {
    __shared__ float tile[32][33];
    const int d0 = blockIdx.x * 32, s0 = blockIdx.y * 32, n = blockIdx.z;
    const int tx = threadIdx.x, ty = threadIdx.y;
#pragma unroll
    for (int j = 0; j < 32; j += 8) {
        int s = s0 + ty + j;
        tile[ty + j][tx] = g_qkv[((size_t)s * N_BATCH + n) * QKV_LD + 2 * E_DIM + d0 + tx];
    }
    __syncthreads();
#pragma unroll
    for (int j = 0; j < 32; j += 8) {
        int d = d0 + ty + j;
        float v = tile[tx][ty + j];
        bf16 h = __float2bfloat16(v);
        bf16 l = __float2bfloat16(v - __bfloat162float(h));
        size_t o = ((size_t)n * E_DIM + d) * T_DIM + s0 + tx;
        g_vth[o] = h;
        g_vtl[o] = l;
    }
}

// ---------------- avg over heads ----------------
__global__ __launch_bounds__(256) void avg_kernel(float* __restrict__ outAvg) {
    const int idx = blockIdx.x * 256 + threadIdx.x;
    const int n = idx >> 18;
    const int rem = idx & 262143;
    float4 acc = make_float4(0.f, 0.f, 0.f, 0.f);
#pragma unroll
    for (int h = 0; h < 16; h++) {
        const size_t base = ((size_t)(n * 16 + h) << 20) + (size_t)rem * 4;
        union { uint2 u; __nv_bfloat162 b[2]; } Hv, Lv;
        Hv.u = *reinterpret_cast<const uint2*>(g_ph + base);
        Lv.u = *reinterpret_cast<const uint2*>(g_pl + base);
        float2 a0 = __bfloat1622float2(Hv.b[0]), a1 = __bfloat1622float2(Hv.b[1]);
        float2 b0 = __bfloat1622float2(Lv.b[0]), b1 = __bfloat1622float2(Lv.b[1]);
        acc.x += a0.x + b0.x; acc.y += a0.y + b0.y;
        acc.z += a1.x + b1.x; acc.w += a1.y + b1.y;
    }
    const float sc = 1.f / 16.f;
    *reinterpret_cast<float4*>(outAvg + (size_t)idx * 4) =
        make_float4(acc.x * sc, acc.y * sc, acc.z * sc, acc.w * sc);
}

// ---------------- host ----------------
extern "C" void kernel_launch(void* const* d_in, const int* in_sizes, int n_in,
                              void* d_out, int out_size) {
    (void)in_sizes; (void)n_in; (void)out_size;
    const float* query = (const float*)d_in[0];
    const float* in_w  = (const float*)d_in[3];
    const float* in_b  = (const float*)d_in[4];
    const float* out_w = (const float*)d_in[5];
    const float* out_b = (const float*)d_in[6];
    float* out = (float*)d_out;
    float* avg = out + (size_t)M_ROWS * E_DIM;

    void *qh, *ql, *wih, *wil, *woh, *wol, *qkv, *qkvh, *qkvl, *ctx, *ch, *cl;
    cudaGetSymbolAddress(&qh,  g_qh);  cudaGetSymbolAddress(&ql,  g_ql);
    cudaGetSymbolAddress(&wih, g_wih); cudaGetSymbolAddress(&wil, g_wil);
    cudaGetSymbolAddress(&woh, g_woh); cudaGetSymbolAddress(&wol, g_wol);
    cudaGetSymbolAddress(&qkv, g_qkv);
    cudaGetSymbolAddress(&qkvh, g_qkvh); cudaGetSymbolAddress(&qkvl, g_qkvl);
    cudaGetSymbolAddress(&ctx, g_ctx);
    cudaGetSymbolAddress(&ch,  g_ch);  cudaGetSymbolAddress(&cl,  g_cl);

    cudaFuncSetAttribute(k_qkv,       cudaFuncAttributeMaxDynamicSharedMemorySize, SMEM_128);
    cudaFuncSetAttribute(k_scores_sm, cudaFuncAttributeMaxDynamicSharedMemorySize, SC_SMEM);
    cudaFuncSetAttribute(k_pv,        cudaFuncAttributeMaxDynamicSharedMemorySize, SMEM_64);
    cudaFuncSetAttribute(k_out,       cudaFuncAttributeMaxDynamicSharedMemorySize, SMEM_128);

    split_kernel<<<(M_ROWS * E_DIM / 4) / 256, 256>>>(query, (bf16*)qh, (bf16*)ql);
    split_kernel<<<(QKV_LD * E_DIM / 4) / 256, 256>>>(in_w, (bf16*)wih, (bf16*)wil);
    split_kernel<<<(E_DIM * E_DIM / 4) / 256, 256>>>(out_w, (bf16*)woh, (bf16*)wol);

    // 1) QKV projection
    k_qkv<<<dim3(QKV_LD / 128, M_ROWS / 128), 256, SMEM_128>>>(in_b);

    // 2) split qkv; transpose+split V
    split_kernel<<<((size_t)M_ROWS * QKV_LD / 4) / 256, 256>>>(
        (const float*)qkv, (bf16*)qkvh, (bf16*)qkvl);
    vt_kernel<<<dim3(E_DIM / 32, T_DIM / 32, N_BATCH), dim3(32, 8)>>>();

    // 3) fused scores + softmax -> (p_hi, p_lo)
    k_scores_sm<<<dim3(T_DIM / 128, B_HEADS), 256, SC_SMEM>>>();

    // 4) head-averaged weights -> second output
    avg_kernel<<<(N_BATCH * T_DIM * T_DIM / 4) / 256, 256>>>(avg);

    // 5) PV -> g_ctx
    k_pv<<<dim3(T_DIM / 128, B_HEADS), 256, SMEM_64>>>();

    // 6) split ctx; out-projection -> first output
    split_kernel<<<(M_ROWS * E_DIM / 4) / 256, 256>>>((const float*)ctx, (bf16*)ch, (bf16*)cl);
    k_out<<<dim3(E_DIM / 128, M_ROWS / 128), 256, SMEM_128>>>(out_b, out);
}